// round 5
// baseline (speedup 1.0000x reference)
#include <cuda_runtime.h>
#include <math.h>

#define EPSN 1e-12f

// One CTA handles one (n, h, x-tile of TX). Loads L tile (C x TX) and the
// R halo tile (C x (TX + D - 1)) into shared memory, computes per-column
// inverse L2 norms in shared memory, then computes the banded Gram products
// with RDxRX register blocking. Normalization is applied in the epilogue:
//   out[d][x] = (sum_c L[c][x] * R[c][x-d]) * invl[x] * invr[x-d]
// which is numerically identical (to fp32 rounding) to normalizing first.
//
// RX == 4 is required: it makes the per-thread shared loads exactly one
// float4 and the warp's lane stride one float4 => fully coalesced,
// conflict-free LDS.128 for both the L and R tiles.

template<int C, int D, int TX, int RD, int RX, int SRP, int NT>
__global__ __launch_bounds__(NT)
void cost_volume_kernel(const float* __restrict__ Lp,
                        const float* __restrict__ Rp,
                        float* __restrict__ out,
                        int H, int W)
{
    static_assert(RX == 4, "RX must be 4 (float4 lane-contiguous LDS)");
    static_assert(TX % RX == 0 && D % RD == 0, "tiling");
    static_assert((D / RD) * (TX / RX) == NT, "thread count");

    extern __shared__ float smem[];
    float* sl   = smem;                 // C * TX
    float* sr   = smem + C * TX;        // C * SRP  (SRP >= TX + D - 1 + 1, mult of 4)
    float* invl = sr + C * SRP;         // TX
    float* invr = invl + TX;            // SRP

    const int n   = blockIdx.z;
    const int h   = blockIdx.y;
    const int xb  = blockIdx.x * TX;
    const int tid = threadIdx.x;

    const int plane = ((n * C) * H + h) * W;   // + c*H*W per channel
    const int HW = H * W;

    // ---- cooperative tile loads (coalesced: TX/SRP-wide rows) ----
    #pragma unroll 1
    for (int idx = tid; idx < C * TX; idx += NT) {
        int c = idx / TX, x = idx % TX;
        sl[idx] = Lp[plane + c * HW + xb + x];
    }
    const int y0 = xb - (D - 1);
    #pragma unroll 1
    for (int idx = tid; idx < C * SRP; idx += NT) {
        int c = idx / SRP, col = idx % SRP;
        int y = y0 + col;
        sr[idx] = (y >= 0 && y < W) ? Rp[plane + c * HW + y] : 0.0f;
    }
    __syncthreads();

    // ---- per-column inverse norms (lane-stride-1 => conflict-free) ----
    for (int t = tid; t < TX; t += NT) {
        float ss = 0.0f;
        #pragma unroll
        for (int c = 0; c < C; ++c) { float v = sl[c * TX + t]; ss = fmaf(v, v, ss); }
        invl[t] = 1.0f / fmaxf(sqrtf(ss), EPSN);
    }
    for (int t = tid; t < SRP; t += NT) {
        float ss = 0.0f;
        #pragma unroll
        for (int c = 0; c < C; ++c) { float v = sr[c * SRP + t]; ss = fmaf(v, v, ss); }
        invr[t] = 1.0f / fmaxf(sqrtf(ss), EPSN);
    }
    __syncthreads();

    // ---- register-blocked banded products ----
    constexpr int BX = TX / RX;
    const int tx = tid % BX;
    const int td = tid / BX;
    const int x0 = tx * RX;            // multiple of 4
    const int d0 = td * RD;            // multiple of RD
    // sr column for (x local = x0+j, d = d0+i) is  x0 + j + (D-1) - d0 - i.
    // Minimum over the thread's block:
    const int rbase = x0 + (D - 1) - d0 - (RD - 1);   // multiple of 4

    float acc[RD][RX];
    #pragma unroll
    for (int i = 0; i < RD; ++i)
        #pragma unroll
        for (int j = 0; j < RX; ++j) acc[i][j] = 0.0f;

    constexpr int NV  = RX + RD - 1;       // distinct r values needed
    constexpr int NR4 = (NV + 3) / 4;      // float4 loads (may fetch 1 extra)

    #pragma unroll 2
    for (int c = 0; c < C; ++c) {
        float lv[RX];
        *(float4*)lv = *(const float4*)&sl[c * TX + x0];
        float rv[NR4 * 4];
        #pragma unroll
        for (int q = 0; q < NR4; ++q)
            *(float4*)&rv[q * 4] = *(const float4*)&sr[c * SRP + rbase + q * 4];
        #pragma unroll
        for (int i = 0; i < RD; ++i)
            #pragma unroll
            for (int j = 0; j < RX; ++j)
                acc[i][j] = fmaf(lv[j], rv[j + (RD - 1 - i)], acc[i][j]);
    }

    // ---- epilogue: normalize, mask x<d, float4 stores ----
    #pragma unroll
    for (int i = 0; i < RD; ++i) {
        const int d = d0 + i;
        float4 o;
        float* op = (float*)&o;
        #pragma unroll
        for (int j = 0; j < RX; ++j) {
            const int xg  = xb + x0 + j;
            const int col = x0 + j + (D - 1) - d;
            op[j] = (xg >= d) ? acc[i][j] * invl[x0 + j] * invr[col] : 0.0f;
        }
        *(float4*)&out[((n * D + d) * H + h) * W + xb + x0] = o;
    }
}

extern "C" void kernel_launch(void* const* d_in, const int* in_sizes, int n_in,
                              void* d_out, int out_size)
{
    const float* l0 = (const float*)d_in[0];
    const float* r0 = (const float*)d_in[1];
    const float* l1 = (const float*)d_in[2];
    const float* r1 = (const float*)d_in[3];
    const float* l2 = (const float*)d_in[4];
    const float* r2 = (const float*)d_in[5];
    float* out = (float*)d_out;

    // max_disparity is 128 by construction (setup_inputs), min(128, 512) = 128.
    // Level D: 128, 64, 32.

    // ---- level 0: (2, 32, 256, 512), D=128 ----
    {
        constexpr int C = 32, D = 128, TX = 128, RD = 8, RX = 4;
        constexpr int SRP = 256;                       // >= TX+D-1 (255), mult of 4
        constexpr int NT  = (D / RD) * (TX / RX);      // 512
        constexpr size_t SM = (size_t)(C * TX + C * SRP + TX + SRP) * sizeof(float);
        auto k = cost_volume_kernel<C, D, TX, RD, RX, SRP, NT>;
        cudaFuncSetAttribute(k, cudaFuncAttributeMaxDynamicSharedMemorySize, (int)SM);
        k<<<dim3(512 / TX, 256, 2), NT, SM>>>(l0, r0, out, 256, 512);
    }

    // ---- level 1: (2, 64, 128, 256), D=64 ----
    {
        constexpr int C = 64, D = 64, TX = 128, RD = 8, RX = 4;
        constexpr int SRP = 192;                       // >= 191, mult of 4
        constexpr int NT  = (D / RD) * (TX / RX);      // 256
        constexpr size_t SM = (size_t)(C * TX + C * SRP + TX + SRP) * sizeof(float);
        auto k = cost_volume_kernel<C, D, TX, RD, RX, SRP, NT>;
        cudaFuncSetAttribute(k, cudaFuncAttributeMaxDynamicSharedMemorySize, (int)SM);
        float* out1 = out + (size_t)2 * 128 * 256 * 512;   // + 33,554,432
        k<<<dim3(256 / TX, 128, 2), NT, SM>>>(l1, r1, out1, 128, 256);
    }

    // ---- level 2: (2, 96, 64, 128), D=32 ----
    {
        constexpr int C = 96, D = 32, TX = 128, RD = 4, RX = 4;
        constexpr int SRP = 160;                       // >= 159, mult of 4
        constexpr int NT  = (D / RD) * (TX / RX);      // 256
        constexpr size_t SM = (size_t)(C * TX + C * SRP + TX + SRP) * sizeof(float);
        auto k = cost_volume_kernel<C, D, TX, RD, RX, SRP, NT>;
        cudaFuncSetAttribute(k, cudaFuncAttributeMaxDynamicSharedMemorySize, (int)SM);
        float* out2 = out + (size_t)2 * 128 * 256 * 512 + (size_t)2 * 64 * 128 * 256;
        k<<<dim3(128 / TX, 64, 2), NT, SM>>>(l2, r2, out2, 64, 128);
    }
}